// round 4
// baseline (speedup 1.0000x reference)
#include <cuda_runtime.h>
#include <cstdint>
#include <math.h>

#define BB 8
#define RR 256
#define DD 128
#define NROW (BB*RR)
#define NEG 0.1f
#define SXW 132            // X row stride (words): %32 == 4  -> conflict-free A frags
#define SWW 136            // W row stride (words): %32 == 8  -> conflict-free B frags

// Persistent scratch (no allocations allowed)
__device__ float g_h[NROW*DD];
__device__ float g_ti[NROW*DD];
__device__ float g_tj[NROW*DD];
__device__ float g_mpre[NROW*DD];

__device__ __forceinline__ float lrelu(float x){ return x > 0.f ? x : NEG*x; }

__device__ __forceinline__ float rna_tf32(float x){
    uint32_t u;
    asm("cvt.rna.tf32.f32 %0, %1;" : "=r"(u) : "f"(x));
    return __uint_as_float(u);
}

// ---------------------------------------------------------------------------
// K1: h = leaky(fres @ W_emb)
// ---------------------------------------------------------------------------
__global__ void k_embed(const float* __restrict__ fres, const float* __restrict__ Wemb){
    int row = blockIdx.x, c = threadIdx.x;
    __shared__ float sf[20];
    if (c < 20) sf[c] = fres[row*20 + c];
    __syncthreads();
    float acc = 0.f;
    #pragma unroll
    for (int k = 0; k < 20; k++) acc += sf[k]*Wemb[k*DD + c];
    g_h[(size_t)row*DD + c] = lrelu(acc);
}

// ---------------------------------------------------------------------------
// K3: ti/tj, 4 rows per block (weight LDG amortized over 4 FFMAs)
// ---------------------------------------------------------------------------
__global__ void k_titj4(const float* __restrict__ We1, const float* __restrict__ be1){
    const int r0 = blockIdx.x*4, c = threadIdx.x;
    __shared__ float sh[4][DD];
    #pragma unroll
    for (int r = 0; r < 4; r++) sh[r][c] = g_h[(size_t)(r0+r)*DD + c];
    __syncthreads();
    float ai[4] = {0,0,0,0}, aj[4] = {0,0,0,0};
    #pragma unroll 2
    for (int k = 0; k < DD; k++){
        float wi = We1[k*DD + c];
        float wj = We1[(DD + k)*DD + c];
        #pragma unroll
        for (int r = 0; r < 4; r++){
            float hv = sh[r][k];
            ai[r] += hv*wi;
            aj[r] += hv*wj;
        }
    }
    const float be = be1[c];
    #pragma unroll
    for (int r = 0; r < 4; r++){
        g_ti[(size_t)(r0+r)*DD + c] = ai[r] + be;
        g_tj[(size_t)(r0+r)*DD + c] = aj[r];
    }
}

// ---------------------------------------------------------------------------
// K5a: fused node update + titj for the NEXT iteration (4 rows per block)
// ---------------------------------------------------------------------------
__global__ void k_update_titj4(const float* __restrict__ Wh1, const float* __restrict__ bh1,
                               const float* __restrict__ Wh2, const float* __restrict__ bh2,
                               const float* __restrict__ We1, const float* __restrict__ be1)
{
    const int r0 = blockIdx.x*4, c = threadIdx.x;
    __shared__ float shm[4][2*DD];
    __shared__ float su[4][DD];
    __shared__ float sn[4][DD];
    #pragma unroll
    for (int r = 0; r < 4; r++){
        shm[r][c]      = g_h[(size_t)(r0+r)*DD + c];
        shm[r][DD + c] = g_mpre[(size_t)(r0+r)*DD + c];
    }
    __syncthreads();
    float a[4] = {0,0,0,0};
    #pragma unroll 2
    for (int k = 0; k < 2*DD; k++){
        float wv = Wh1[k*DD + c];
        #pragma unroll
        for (int r = 0; r < 4; r++) a[r] += shm[r][k]*wv;
    }
    const float b1 = bh1[c];
    #pragma unroll
    for (int r = 0; r < 4; r++) su[r][c] = lrelu(a[r] + b1);
    __syncthreads();
    float a2[4] = {0,0,0,0};
    #pragma unroll 2
    for (int k = 0; k < DD; k++){
        float wv = Wh2[k*DD + c];
        #pragma unroll
        for (int r = 0; r < 4; r++) a2[r] += su[r][k]*wv;
    }
    const float b2 = bh2[c];
    #pragma unroll
    for (int r = 0; r < 4; r++){
        float hn = a2[r] + b2 + shm[r][c];
        sn[r][c] = hn;
        g_h[(size_t)(r0+r)*DD + c] = hn;
    }
    __syncthreads();
    // titj on the freshly updated h
    float ai[4] = {0,0,0,0}, aj[4] = {0,0,0,0};
    #pragma unroll 2
    for (int k = 0; k < DD; k++){
        float wi = We1[k*DD + c];
        float wj = We1[(DD + k)*DD + c];
        #pragma unroll
        for (int r = 0; r < 4; r++){
            float hv = sn[r][k];
            ai[r] += hv*wi;
            aj[r] += hv*wj;
        }
    }
    const float be = be1[c];
    #pragma unroll
    for (int r = 0; r < 4; r++){
        g_ti[(size_t)(r0+r)*DD + c] = ai[r] + be;
        g_tj[(size_t)(r0+r)*DD + c] = aj[r];
    }
}

// ---------------------------------------------------------------------------
// K5b: final node update, writes result (4 rows per block)
// ---------------------------------------------------------------------------
__global__ void k_update_out4(const float* __restrict__ Wh1, const float* __restrict__ bh1,
                              const float* __restrict__ Wh2, const float* __restrict__ bh2,
                              float* __restrict__ out)
{
    const int r0 = blockIdx.x*4, c = threadIdx.x;
    __shared__ float shm[4][2*DD];
    __shared__ float su[4][DD];
    #pragma unroll
    for (int r = 0; r < 4; r++){
        shm[r][c]      = g_h[(size_t)(r0+r)*DD + c];
        shm[r][DD + c] = g_mpre[(size_t)(r0+r)*DD + c];
    }
    __syncthreads();
    float a[4] = {0,0,0,0};
    #pragma unroll 2
    for (int k = 0; k < 2*DD; k++){
        float wv = Wh1[k*DD + c];
        #pragma unroll
        for (int r = 0; r < 4; r++) a[r] += shm[r][k]*wv;
    }
    const float b1 = bh1[c];
    #pragma unroll
    for (int r = 0; r < 4; r++) su[r][c] = lrelu(a[r] + b1);
    __syncthreads();
    float a2[4] = {0,0,0,0};
    #pragma unroll 2
    for (int k = 0; k < DD; k++){
        float wv = Wh2[k*DD + c];
        #pragma unroll
        for (int r = 0; r < 4; r++) a2[r] += su[r][k]*wv;
    }
    const float b2 = bh2[c];
    #pragma unroll
    for (int r = 0; r < 4; r++)
        out[(size_t)(r0+r)*DD + c] = a2[r] + b2 + shm[r][c];
}

// ---------------------------------------------------------------------------
// K4: edge kernel — tf32 mma.sync, persistent grid=148, 8 warps = 4(j) x 2(c)
// ---------------------------------------------------------------------------
__global__ void __launch_bounds__(256, 1)
k_edge(const float* __restrict__ be2,
       const float* __restrict__ Winf,
       const float* __restrict__ binf,
       const float* __restrict__ We1,
       const float* __restrict__ We2,
       const float* __restrict__ coords,
       int ntiles)
{
    extern __shared__ float sm[];
    float* sW  = sm;                    // 128*SWW
    float* sX  = sW  + DD*SWW;          // 256*SXW
    float* sC  = sX  + RR*SXW;          // 3*256
    float* sEp = sC  + 3*RR;            // 256
    float* sE  = sEp + RR;              // 256
    float* sTi = sE  + RR;              // 128
    float* sWd = sTi + DD;              // 128
    float* sMp = sWd + DD;              // 128
    float* sBc = sMp + DD;              // 128
    float* sWc = sBc + DD;              // 128

    const int t    = threadIdx.x;
    const int w    = t >> 5;
    const int lane = t & 31;
    const int g    = lane >> 2;         // 0..7
    const int tig  = lane & 3;          // 0..3
    const int jbase = (w >> 1) * 64;
    const int cbase = (w & 1) * 64;

    // one-time staging: rounded W_e2, w_d, biases
    for (int idx = t; idx < DD*DD; idx += 256) {
        int k = idx >> 7, c = idx & 127;
        sW[k*SWW + c] = rna_tf32(We2[idx]);
    }
    if (t < DD) {
        sWd[t] = We1[2*DD*DD + t];
        sBc[t] = be2[t];
        sWc[t] = Winf[t];
    }
    const float bi = binf[0];
    __syncthreads();

    for (int tile = blockIdx.x; tile < ntiles; tile += gridDim.x) {
        const int b = tile >> 8, i = tile & 255;

        // ---- per-tile staging (one barrier) ----
        {
            const float* cp = coords + ((size_t)b*RR + t)*3;
            sC[t] = cp[0]; sC[RR + t] = cp[1]; sC[2*RR + t] = cp[2];
        }
        if (t < DD) { sTi[t] = g_ti[(size_t)tile*DD + t]; sMp[t] = 0.f; }
        sEp[t] = 0.f;
        __syncthreads();

        // ---- build X (warp per j row, lane per k-quad); d2 computed inline ----
        {
            const float* tjb = g_tj + (size_t)b*RR*DD;
            const int k4 = lane*4;
            const float ti0 = sTi[k4], ti1 = sTi[k4+1], ti2 = sTi[k4+2], ti3 = sTi[k4+3];
            const float wd0 = sWd[k4], wd1 = sWd[k4+1], wd2 = sWd[k4+2], wd3 = sWd[k4+3];
            const float cix = sC[i], ciy = sC[RR + i], ciz = sC[2*RR + i];
            #pragma unroll
            for (int j = w; j < RR; j += 16) {
                const int j1 = j + 8;
                float4 tv0 = *(const float4*)&tjb[(size_t)j *DD + k4];
                float4 tv1 = *(const float4*)&tjb[(size_t)j1*DD + k4];
                float dx0 = sC[j ] - cix, dy0 = sC[RR+j ] - ciy, dz0 = sC[2*RR+j ] - ciz;
                float dx1 = sC[j1] - cix, dy1 = sC[RR+j1] - ciy, dz1 = sC[2*RR+j1] - ciz;
                float d20 = dx0*dx0 + dy0*dy0 + dz0*dz0;
                float d21 = dx1*dx1 + dy1*dy1 + dz1*dz1;
                *(float4*)&sX[j*SXW + k4] = make_float4(
                    rna_tf32(lrelu(ti0 + tv0.x + d20*wd0)),
                    rna_tf32(lrelu(ti1 + tv0.y + d20*wd1)),
                    rna_tf32(lrelu(ti2 + tv0.z + d20*wd2)),
                    rna_tf32(lrelu(ti3 + tv0.w + d20*wd3)));
                *(float4*)&sX[j1*SXW + k4] = make_float4(
                    rna_tf32(lrelu(ti0 + tv1.x + d21*wd0)),
                    rna_tf32(lrelu(ti1 + tv1.y + d21*wd1)),
                    rna_tf32(lrelu(ti2 + tv1.z + d21*wd2)),
                    rna_tf32(lrelu(ti3 + tv1.w + d21*wd3)));
            }
        }
        __syncthreads();

        // ---- mainloop: 64x64 warp tile, m16n8k8 tf32 ----
        float acc[4][8][4];
        #pragma unroll
        for (int mi = 0; mi < 4; mi++)
            #pragma unroll
            for (int ni = 0; ni < 8; ni++)
                #pragma unroll
                for (int q = 0; q < 4; q++) acc[mi][ni][q] = 0.f;

        #pragma unroll 4
        for (int k0 = 0; k0 < DD; k0 += 8) {
            uint32_t A[4][4];
            #pragma unroll
            for (int mi = 0; mi < 4; mi++) {
                const float* xr = sX + (jbase + mi*16 + g)*SXW + k0 + tig;
                A[mi][0] = __float_as_uint(xr[0]);
                A[mi][1] = __float_as_uint(xr[8*SXW]);
                A[mi][2] = __float_as_uint(xr[4]);
                A[mi][3] = __float_as_uint(xr[8*SXW + 4]);
            }
            uint32_t Bf[8][2];
            #pragma unroll
            for (int ni = 0; ni < 8; ni++) {
                const float* wr = sW + (k0 + tig)*SWW + cbase + ni*8 + g;
                Bf[ni][0] = __float_as_uint(wr[0]);
                Bf[ni][1] = __float_as_uint(wr[4*SWW]);
            }
            #pragma unroll
            for (int mi = 0; mi < 4; mi++)
                #pragma unroll
                for (int ni = 0; ni < 8; ni++)
                    asm volatile(
                        "mma.sync.aligned.m16n8k8.row.col.f32.tf32.tf32.f32 "
                        "{%0,%1,%2,%3}, {%4,%5,%6,%7}, {%8,%9}, {%0,%1,%2,%3};"
                        : "+f"(acc[mi][ni][0]), "+f"(acc[mi][ni][1]),
                          "+f"(acc[mi][ni][2]), "+f"(acc[mi][ni][3])
                        : "r"(A[mi][0]), "r"(A[mi][1]), "r"(A[mi][2]), "r"(A[mi][3]),
                          "r"(Bf[ni][0]), "r"(Bf[ni][1]));
        }

        // ---- epilogue ----
        float bc[16], wc[16];
        #pragma unroll
        for (int ni = 0; ni < 8; ni++)
            #pragma unroll
            for (int q = 0; q < 2; q++) {
                int c = cbase + ni*8 + tig*2 + q;
                bc[ni*2+q] = sBc[c];
                wc[ni*2+q] = sWc[c];
            }

        // pass 1: per-j gate logit partials
        #pragma unroll
        for (int mi = 0; mi < 4; mi++)
            #pragma unroll
            for (int r = 0; r < 2; r++) {
                float p = 0.f;
                #pragma unroll
                for (int ni = 0; ni < 8; ni++)
                    #pragma unroll
                    for (int q = 0; q < 2; q++)
                        p += lrelu(acc[mi][ni][r*2+q] + bc[ni*2+q]) * wc[ni*2+q];
                p += __shfl_xor_sync(0xffffffffu, p, 1);
                p += __shfl_xor_sync(0xffffffffu, p, 2);
                if (tig == 0) atomicAdd(&sEp[jbase + mi*16 + g + r*8], p);
            }
        __syncthreads();
        {
            float s = sEp[t] + bi;
            sE[t] = (t == i) ? 0.f : __fdividef(1.f, 1.f + __expf(-s));
        }
        __syncthreads();

        // pass 2: mpre[c] = sum_j m*e
        float macc[16];
        #pragma unroll
        for (int q = 0; q < 16; q++) macc[q] = 0.f;
        #pragma unroll
        for (int mi = 0; mi < 4; mi++)
            #pragma unroll
            for (int r = 0; r < 2; r++) {
                float e = sE[jbase + mi*16 + g + r*8];
                #pragma unroll
                for (int ni = 0; ni < 8; ni++)
                    #pragma unroll
                    for (int q = 0; q < 2; q++)
                        macc[ni*2+q] += lrelu(acc[mi][ni][r*2+q] + bc[ni*2+q]) * e;
            }
        #pragma unroll
        for (int q = 0; q < 16; q++) {
            macc[q] += __shfl_xor_sync(0xffffffffu, macc[q], 4);
            macc[q] += __shfl_xor_sync(0xffffffffu, macc[q], 8);
            macc[q] += __shfl_xor_sync(0xffffffffu, macc[q], 16);
        }
        if (g == 0) {
            #pragma unroll
            for (int q = 0; q < 16; q++)
                atomicAdd(&sMp[cbase + (q >> 1)*8 + tig*2 + (q & 1)], macc[q]);
        }
        __syncthreads();
        if (t < DD) g_mpre[(size_t)tile*DD + t] = sMp[t];
        __syncthreads();
    }
}

// ---------------------------------------------------------------------------
extern "C" void kernel_launch(void* const* d_in, const int* in_sizes, int n_in,
                              void* d_out, int out_size)
{
    const float* fres   = (const float*)d_in[0];
    const float* coords = (const float*)d_in[1];
    const float* Wemb   = (const float*)d_in[2];
    const float* We1    = (const float*)d_in[3];
    const float* be1    = (const float*)d_in[4];
    const float* We2    = (const float*)d_in[5];
    const float* be2    = (const float*)d_in[6];
    const float* Winf   = (const float*)d_in[7];
    const float* binf   = (const float*)d_in[8];
    const float* Wh1    = (const float*)d_in[9];
    const float* bh1    = (const float*)d_in[10];
    const float* Wh2    = (const float*)d_in[11];
    const float* bh2    = (const float*)d_in[12];
    float* out = (float*)d_out;

    const int EDGE_SMEM = (DD*SWW + RR*SXW + 3*RR + RR + RR + 5*DD) * (int)sizeof(float);
    cudaFuncSetAttribute(k_edge, cudaFuncAttributeMaxDynamicSharedMemorySize, EDGE_SMEM);

    k_embed<<<NROW, DD>>>(fres, Wemb);
    k_titj4<<<NROW/4, DD>>>(We1, be1);
    k_edge<<<148, 256, EDGE_SMEM>>>(be2, Winf, binf, We1, We2, coords, NROW);
    k_update_titj4<<<NROW/4, DD>>>(Wh1, bh1, Wh2, bh2, We1, be1);
    k_edge<<<148, 256, EDGE_SMEM>>>(be2, Winf, binf, We1, We2, coords, NROW);
    k_update_out4<<<NROW/4, DD>>>(Wh1, bh1, Wh2, bh2, out);
}

// round 6
// speedup vs baseline: 1.7662x; 1.7662x over previous
#include <cuda_runtime.h>
#include <cstdint>
#include <math.h>

#define BB 8
#define RR 256
#define DD 128
#define NROW (BB*RR)
#define NEG 0.1f
#define SXW 132            // X row stride (words): %32 == 4  -> conflict-free A frags
#define SWW 136            // W row stride (words): %32 == 8  -> conflict-free B frags

// Persistent scratch (no allocations allowed)
__device__ float g_h[NROW*DD];
__device__ float g_ti[NROW*DD];
__device__ float g_tj[NROW*DD];
__device__ float g_mpre[NROW*DD];
__device__ float g_u[NROW*DD];

__device__ __forceinline__ float lrelu(float x){ return x > 0.f ? x : NEG*x; }

__device__ __forceinline__ float rna_tf32(float x){
    uint32_t u;
    asm("cvt.rna.tf32.f32 %0, %1;" : "=r"(u) : "f"(x));
    return __uint_as_float(u);
}

// ---------------------------------------------------------------------------
// K1: h = leaky(fres @ W_emb)
// ---------------------------------------------------------------------------
__global__ void k_embed(const float* __restrict__ fres, const float* __restrict__ Wemb){
    int row = blockIdx.x, c = threadIdx.x;
    __shared__ float sf[20];
    if (c < 20) sf[c] = fres[row*20 + c];
    __syncthreads();
    float acc = 0.f;
    #pragma unroll
    for (int k = 0; k < 20; k++) acc += sf[k]*Wemb[k*DD + c];
    g_h[(size_t)row*DD + c] = lrelu(acc);
}

// ---------------------------------------------------------------------------
// Tiled fp32 GEMM aux kernels: block tile 32(M) x 64(N), 256 threads,
// per-thread 4x2 register blocking, operands fully staged in smem.
// ---------------------------------------------------------------------------

// ti|tj = h @ [W_i | W_j]  (+be1 on ti).  Grid = (2048/32) * (256/64) = 256.
__global__ void __launch_bounds__(256)
k_titj_g(const float* __restrict__ We1, const float* __restrict__ be1){
    __shared__ float sA[32*DD];        // 16KB
    __shared__ float sW[DD*64];        // 32KB
    const int t = threadIdx.x;
    const int bm = blockIdx.x >> 2, bn = blockIdx.x & 3;
    const int row0 = bm*32;
    const int ncol0 = bn*64;           // 0,64 -> ti ; 128,192 -> tj

    {   // A tile: 32 x 128
        const float4* src = (const float4*)(g_h + (size_t)row0*DD);
        float4* dst = (float4*)sA;
        #pragma unroll
        for (int idx = t; idx < 32*DD/4; idx += 256) dst[idx] = src[idx];
    }
    {   // W tile: 128(k) x 64(n)
        const int koff = (ncol0 >= DD) ? DD : 0;
        const int c0g  = ncol0 & (DD-1);
        #pragma unroll
        for (int idx = t; idx < DD*16; idx += 256) {
            int k = idx >> 4, cc = (idx & 15)*4;
            *(float4*)&sW[k*64 + cc] =
                *(const float4*)&We1[(size_t)(koff + k)*DD + c0g + cc];
        }
    }
    __syncthreads();

    const int r0 = (t >> 5)*4, c0 = (t & 31)*2;
    float a00=0,a01=0,a10=0,a11=0,a20=0,a21=0,a30=0,a31=0;
    #pragma unroll 4
    for (int k = 0; k < DD; k++){
        float2 wv = *(const float2*)&sW[k*64 + c0];
        float v0 = sA[(r0+0)*DD + k];
        float v1 = sA[(r0+1)*DD + k];
        float v2 = sA[(r0+2)*DD + k];
        float v3 = sA[(r0+3)*DD + k];
        a00 += v0*wv.x; a01 += v0*wv.y;
        a10 += v1*wv.x; a11 += v1*wv.y;
        a20 += v2*wv.x; a21 += v2*wv.y;
        a30 += v3*wv.x; a31 += v3*wv.y;
    }
    if (ncol0 < DD) {
        const float b0 = be1[ncol0 + c0], b1v = be1[ncol0 + c0 + 1];
        float* o = g_ti + (size_t)(row0 + r0)*DD + ncol0 + c0;
        o[0] = a00+b0; o[1] = a01+b1v; o += DD;
        o[0] = a10+b0; o[1] = a11+b1v; o += DD;
        o[0] = a20+b0; o[1] = a21+b1v; o += DD;
        o[0] = a30+b0; o[1] = a31+b1v;
    } else {
        float* o = g_tj + (size_t)(row0 + r0)*DD + (ncol0 - DD) + c0;
        o[0] = a00; o[1] = a01; o += DD;
        o[0] = a10; o[1] = a11; o += DD;
        o[0] = a20; o[1] = a21; o += DD;
        o[0] = a30; o[1] = a31;
    }
}

// u = lrelu([h, mpre] @ Wh1 + bh1).  K=256 in 2 chunks.  Grid = 64*2 = 128.
__global__ void __launch_bounds__(256)
k_u1_g(const float* __restrict__ Wh1, const float* __restrict__ bh1){
    __shared__ float sA[32*DD];        // 16KB (k-chunk of A)
    __shared__ float sW[DD*64];        // 32KB (k-chunk of W)
    const int t = threadIdx.x;
    const int bm = blockIdx.x >> 1, bn = blockIdx.x & 1;
    const int row0 = bm*32, ncol0 = bn*64;
    const int r0 = (t >> 5)*4, c0 = (t & 31)*2;

    float a00=0,a01=0,a10=0,a11=0,a20=0,a21=0,a30=0,a31=0;
    #pragma unroll
    for (int ch = 0; ch < 2; ch++){
        {
            const float* base = (ch == 0) ? g_h : g_mpre;
            const float4* src = (const float4*)(base + (size_t)row0*DD);
            float4* dst = (float4*)sA;
            #pragma unroll
            for (int idx = t; idx < 32*DD/4; idx += 256) dst[idx] = src[idx];
        }
        #pragma unroll
        for (int idx = t; idx < DD*16; idx += 256) {
            int k = idx >> 4, cc = (idx & 15)*4;
            *(float4*)&sW[k*64 + cc] =
                *(const float4*)&Wh1[(size_t)(ch*DD + k)*DD + ncol0 + cc];
        }
        __syncthreads();
        #pragma unroll 4
        for (int k = 0; k < DD; k++){
            float2 wv = *(const float2*)&sW[k*64 + c0];
            float v0 = sA[(r0+0)*DD + k];
            float v1 = sA[(r0+1)*DD + k];
            float v2 = sA[(r0+2)*DD + k];
            float v3 = sA[(r0+3)*DD + k];
            a00 += v0*wv.x; a01 += v0*wv.y;
            a10 += v1*wv.x; a11 += v1*wv.y;
            a20 += v2*wv.x; a21 += v2*wv.y;
            a30 += v3*wv.x; a31 += v3*wv.y;
        }
        __syncthreads();
    }
    const float b0 = bh1[ncol0 + c0], b1v = bh1[ncol0 + c0 + 1];
    float* o = g_u + (size_t)(row0 + r0)*DD + ncol0 + c0;
    o[0] = lrelu(a00+b0); o[1] = lrelu(a01+b1v); o += DD;
    o[0] = lrelu(a10+b0); o[1] = lrelu(a11+b1v); o += DD;
    o[0] = lrelu(a20+b0); o[1] = lrelu(a21+b1v); o += DD;
    o[0] = lrelu(a30+b0); o[1] = lrelu(a31+b1v);
}

// hnew = u @ Wh2 + bh2 + h.  Writes g_h (out==null) or out.  Grid = 128.
__global__ void __launch_bounds__(256)
k_u2_g(const float* __restrict__ Wh2, const float* __restrict__ bh2,
       float* __restrict__ out){
    __shared__ float sA[32*DD];
    __shared__ float sW[DD*64];
    const int t = threadIdx.x;
    const int bm = blockIdx.x >> 1, bn = blockIdx.x & 1;
    const int row0 = bm*32, ncol0 = bn*64;

    {
        const float4* src = (const float4*)(g_u + (size_t)row0*DD);
        float4* dst = (float4*)sA;
        #pragma unroll
        for (int idx = t; idx < 32*DD/4; idx += 256) dst[idx] = src[idx];
    }
    #pragma unroll
    for (int idx = t; idx < DD*16; idx += 256) {
        int k = idx >> 4, cc = (idx & 15)*4;
        *(float4*)&sW[k*64 + cc] = *(const float4*)&Wh2[(size_t)k*DD + ncol0 + cc];
    }
    __syncthreads();

    const int r0 = (t >> 5)*4, c0 = (t & 31)*2;
    float a00=0,a01=0,a10=0,a11=0,a20=0,a21=0,a30=0,a31=0;
    #pragma unroll 4
    for (int k = 0; k < DD; k++){
        float2 wv = *(const float2*)&sW[k*64 + c0];
        float v0 = sA[(r0+0)*DD + k];
        float v1 = sA[(r0+1)*DD + k];
        float v2 = sA[(r0+2)*DD + k];
        float v3 = sA[(r0+3)*DD + k];
        a00 += v0*wv.x; a01 += v0*wv.y;
        a10 += v1*wv.x; a11 += v1*wv.y;
        a20 += v2*wv.x; a21 += v2*wv.y;
        a30 += v3*wv.x; a31 += v3*wv.y;
    }
    const float b0 = bh2[ncol0 + c0], b1v = bh2[ncol0 + c0 + 1];
    float* hb = g_h + (size_t)(row0 + r0)*DD + ncol0 + c0;
    float* o  = out ? (out + (size_t)(row0 + r0)*DD + ncol0 + c0) : hb;
    float r;
    r = a00+b0+hb[0];      o[0] = r;
    r = a01+b1v+hb[1];     o[1] = r;  hb += DD; o += DD;
    r = a10+b0+hb[0];      o[0] = r;
    r = a11+b1v+hb[1];     o[1] = r;  hb += DD; o += DD;
    r = a20+b0+hb[0];      o[0] = r;
    r = a21+b1v+hb[1];     o[1] = r;  hb += DD; o += DD;
    r = a30+b0+hb[0];      o[0] = r;
    r = a31+b1v+hb[1];     o[1] = r;
}

// ---------------------------------------------------------------------------
// K4: edge kernel — tf32 mma.sync, persistent grid=148, 8 warps = 4(j) x 2(c)
// ---------------------------------------------------------------------------
__global__ void __launch_bounds__(256, 1)
k_edge(const float* __restrict__ be2,
       const float* __restrict__ Winf,
       const float* __restrict__ binf,
       const float* __restrict__ We1,
       const float* __restrict__ We2,
       const float* __restrict__ coords,
       int ntiles)
{
    extern __shared__ float sm[];
    float* sW  = sm;                    // 128*SWW
    float* sX  = sW  + DD*SWW;          // 256*SXW
    float* sC  = sX  + RR*SXW;          // 3*256
    float* sEp = sC  + 3*RR;            // 256
    float* sE  = sEp + RR;              // 256
    float* sTi = sE  + RR;              // 128
    float* sWd = sTi + DD;              // 128
    float* sMp = sWd + DD;              // 128
    float* sBc = sMp + DD;              // 128
    float* sWc = sBc + DD;              // 128

    const int t    = threadIdx.x;
    const int w    = t >> 5;
    const int lane = t & 31;
    const int g    = lane >> 2;
    const int tig  = lane & 3;
    const int jbase = (w >> 1) * 64;
    const int cbase = (w & 1) * 64;

    for (int idx = t; idx < DD*DD; idx += 256) {
        int k = idx >> 7, c = idx & 127;
        sW[k*SWW + c] = rna_tf32(We2[idx]);
    }
    if (t < DD) {
        sWd[t] = We1[2*DD*DD + t];
        sBc[t] = be2[t];
        sWc[t] = Winf[t];
    }
    const float bi = binf[0];
    __syncthreads();

    for (int tile = blockIdx.x; tile < ntiles; tile += gridDim.x) {
        const int b = tile >> 8, i = tile & 255;

        {
            const float* cp = coords + ((size_t)b*RR + t)*3;
            sC[t] = cp[0]; sC[RR + t] = cp[1]; sC[2*RR + t] = cp[2];
        }
        if (t < DD) { sTi[t] = g_ti[(size_t)tile*DD + t]; sMp[t] = 0.f; }
        sEp[t] = 0.f;
        __syncthreads();

        {
            const float* tjb = g_tj + (size_t)b*RR*DD;
            const int k4 = lane*4;
            const float ti0 = sTi[k4], ti1 = sTi[k4+1], ti2 = sTi[k4+2], ti3 = sTi[k4+3];
            const float wd0 = sWd[k4], wd1 = sWd[k4+1], wd2 = sWd[k4+2], wd3 = sWd[k4+3];
            const float cix = sC[i], ciy = sC[RR + i], ciz = sC[2*RR + i];
            #pragma unroll
            for (int j = w; j < RR; j += 16) {
                const int j1 = j + 8;
                float4 tv0 = *(const float4*)&tjb[(size_t)j *DD + k4];
                float4 tv1 = *(const float4*)&tjb[(size_t)j1*DD + k4];
                float dx0 = sC[j ] - cix, dy0 = sC[RR+j ] - ciy, dz0 = sC[2*RR+j ] - ciz;
                float dx1 = sC[j1] - cix, dy1 = sC[RR+j1] - ciy, dz1 = sC[2*RR+j1] - ciz;
                float d20 = dx0*dx0 + dy0*dy0 + dz0*dz0;
                float d21 = dx1*dx1 + dy1*dy1 + dz1*dz1;
                *(float4*)&sX[j*SXW + k4] = make_float4(
                    rna_tf32(lrelu(ti0 + tv0.x + d20*wd0)),
                    rna_tf32(lrelu(ti1 + tv0.y + d20*wd1)),
                    rna_tf32(lrelu(ti2 + tv0.z + d20*wd2)),
                    rna_tf32(lrelu(ti3 + tv0.w + d20*wd3)));
                *(float4*)&sX[j1*SXW + k4] = make_float4(
                    rna_tf32(lrelu(ti0 + tv1.x + d21*wd0)),
                    rna_tf32(lrelu(ti1 + tv1.y + d21*wd1)),
                    rna_tf32(lrelu(ti2 + tv1.z + d21*wd2)),
                    rna_tf32(lrelu(ti3 + tv1.w + d21*wd3)));
            }
        }
        __syncthreads();

        float acc[4][8][4];
        #pragma unroll
        for (int mi = 0; mi < 4; mi++)
            #pragma unroll
            for (int ni = 0; ni < 8; ni++)
                #pragma unroll
                for (int q = 0; q < 4; q++) acc[mi][ni][q] = 0.f;

        #pragma unroll 4
        for (int k0 = 0; k0 < DD; k0 += 8) {
            uint32_t A[4][4];
            #pragma unroll
            for (int mi = 0; mi < 4; mi++) {
                const float* xr = sX + (jbase + mi*16 + g)*SXW + k0 + tig;
                A[mi][0] = __float_as_uint(xr[0]);
                A[mi][1] = __float_as_uint(xr[8*SXW]);
                A[mi][2] = __float_as_uint(xr[4]);
                A[mi][3] = __float_as_uint(xr[8*SXW + 4]);
            }
            uint32_t Bf[8][2];
            #pragma unroll
            for (int ni = 0; ni < 8; ni++) {
                const float* wr = sW + (k0 + tig)*SWW + cbase + ni*8 + g;
                Bf[ni][0] = __float_as_uint(wr[0]);
                Bf[ni][1] = __float_as_uint(wr[4*SWW]);
            }
            #pragma unroll
            for (int mi = 0; mi < 4; mi++)
                #pragma unroll
                for (int ni = 0; ni < 8; ni++)
                    asm volatile(
                        "mma.sync.aligned.m16n8k8.row.col.f32.tf32.tf32.f32 "
                        "{%0,%1,%2,%3}, {%4,%5,%6,%7}, {%8,%9}, {%0,%1,%2,%3};"
                        : "+f"(acc[mi][ni][0]), "+f"(acc[mi][ni][1]),
                          "+f"(acc[mi][ni][2]), "+f"(acc[mi][ni][3])
                        : "r"(A[mi][0]), "r"(A[mi][1]), "r"(A[mi][2]), "r"(A[mi][3]),
                          "r"(Bf[ni][0]), "r"(Bf[ni][1]));
        }

        float bc[16], wc[16];
        #pragma unroll
        for (int ni = 0; ni < 8; ni++)
            #pragma unroll
            for (int q = 0; q < 2; q++) {
                int c = cbase + ni*8 + tig*2 + q;
                bc[ni*2+q] = sBc[c];
                wc[ni*2+q] = sWc[c];
            }

        #pragma unroll
        for (int mi = 0; mi < 4; mi++)
            #pragma unroll
            for (int r = 0; r < 2; r++) {
                float p = 0.f;
                #pragma unroll
                for (int ni = 0; ni < 8; ni++)
                    #pragma unroll
                    for (int q = 0; q < 2; q++)
                        p += lrelu(acc[mi][ni][r*2+q] + bc[ni*2+q]) * wc[ni*2+q];
                p += __shfl_xor_sync(0xffffffffu, p, 1);
                p += __shfl_xor_sync(0xffffffffu, p, 2);
                if (tig == 0) atomicAdd(&sEp[jbase + mi*16 + g + r*8], p);
            }
        __syncthreads();
        {
            float s = sEp[t] + bi;
            sE[t] = (t == i) ? 0.f : __fdividef(1.f, 1.f + __expf(-s));
        }
        __syncthreads();

        float macc[16];
        #pragma unroll
        for (int q = 0; q < 16; q++) macc[q] = 0.f;
        #pragma unroll
        for (int mi = 0; mi < 4; mi++)
            #pragma unroll
            for (int r = 0; r < 2; r++) {
                float e = sE[jbase + mi*16 + g + r*8];
                #pragma unroll
                for (int ni = 0; ni < 8; ni++)
                    #pragma unroll
                    for (int q = 0; q < 2; q++)
                        macc[ni*2+q] += lrelu(acc[mi][ni][r*2+q] + bc[ni*2+q]) * e;
            }
        #pragma unroll
        for (int q = 0; q < 16; q++) {
            macc[q] += __shfl_xor_sync(0xffffffffu, macc[q], 4);
            macc[q] += __shfl_xor_sync(0xffffffffu, macc[q], 8);
            macc[q] += __shfl_xor_sync(0xffffffffu, macc[q], 16);
        }
        if (g == 0) {
            #pragma unroll
            for (int q = 0; q < 16; q++)
                atomicAdd(&sMp[cbase + (q >> 1)*8 + tig*2 + (q & 1)], macc[q]);
        }
        __syncthreads();
        if (t < DD) g_mpre[(size_t)tile*DD + t] = sMp[t];
        __syncthreads();
    }
}

// ---------------------------------------------------------------------------
extern "C" void kernel_launch(void* const* d_in, const int* in_sizes, int n_in,
                              void* d_out, int out_size)
{
    const float* fres   = (const float*)d_in[0];
    const float* coords = (const float*)d_in[1];
    const float* Wemb   = (const float*)d_in[2];
    const float* We1    = (const float*)d_in[3];
    const float* be1    = (const float*)d_in[4];
    const float* We2    = (const float*)d_in[5];
    const float* be2    = (const float*)d_in[6];
    const float* Winf   = (const float*)d_in[7];
    const float* binf   = (const float*)d_in[8];
    const float* Wh1    = (const float*)d_in[9];
    const float* bh1    = (const float*)d_in[10];
    const float* Wh2    = (const float*)d_in[11];
    const float* bh2    = (const float*)d_in[12];
    float* out = (float*)d_out;

    const int EDGE_SMEM = (DD*SWW + RR*SXW + 3*RR + RR + RR + 5*DD) * (int)sizeof(float);
    cudaFuncSetAttribute(k_edge, cudaFuncAttributeMaxDynamicSharedMemorySize, EDGE_SMEM);

    k_embed<<<NROW, DD>>>(fres, Wemb);
    k_titj_g<<<(NROW/32)*4, 256>>>(We1, be1);
    k_edge<<<148, 256, EDGE_SMEM>>>(be2, Winf, binf, We1, We2, coords, NROW);
    k_u1_g<<<(NROW/32)*2, 256>>>(Wh1, bh1);
    k_u2_g<<<(NROW/32)*2, 256>>>(Wh2, bh2, nullptr);
    k_titj_g<<<(NROW/32)*4, 256>>>(We1, be1);
    k_edge<<<148, 256, EDGE_SMEM>>>(be2, Winf, binf, We1, We2, coords, NROW);
    k_u1_g<<<(NROW/32)*2, 256>>>(Wh1, bh1);
    k_u2_g<<<(NROW/32)*2, 256>>>(Wh2, bh2, out);
}

// round 7
// speedup vs baseline: 2.2071x; 1.2496x over previous
#include <cuda_runtime.h>
#include <cuda_fp16.h>
#include <cstdint>
#include <math.h>

#define BB 8
#define RR 256
#define DD 128
#define NROW (BB*RR)
#define NEG 0.1f
#define SXH 136            // X row stride (halves): /2 %32 == 4 -> conflict-free A frags
#define SWH 136            // Wt row stride (halves): same property for B frags

// Persistent scratch (no allocations allowed)
__device__ float g_h[NROW*DD];
__device__ float g_ti[NROW*DD];
__device__ float g_tj[NROW*DD];
__device__ float g_mpre[NROW*DD];
__device__ float g_u[NROW*DD];

__device__ __forceinline__ float lrelu(float x){ return x > 0.f ? x : NEG*x; }

// ---------------------------------------------------------------------------
// K1: h = leaky(fres @ W_emb)
// ---------------------------------------------------------------------------
__global__ void k_embed(const float* __restrict__ fres, const float* __restrict__ Wemb){
    int row = blockIdx.x, c = threadIdx.x;
    __shared__ float sf[20];
    if (c < 20) sf[c] = fres[row*20 + c];
    __syncthreads();
    float acc = 0.f;
    #pragma unroll
    for (int k = 0; k < 20; k++) acc += sf[k]*Wemb[k*DD + c];
    g_h[(size_t)row*DD + c] = lrelu(acc);
}

// ---------------------------------------------------------------------------
// Aux GEMMs: 32(M) x 32(N) tiles, 256 threads, thread = 4 rows x 1 col.
// Operands staged in smem; high grid count for latency hiding.
// ---------------------------------------------------------------------------

// ti|tj = h @ [W_i | W_j] (+be1 on ti).  Grid = 64 * 8 = 512.
__global__ void __launch_bounds__(256)
k_titj_g(const float* __restrict__ We1, const float* __restrict__ be1){
    __shared__ float sA[32*DD];        // 16KB
    __shared__ float sW[DD*32];        // 16KB
    const int t = threadIdx.x;
    const int bm = blockIdx.x >> 3, bn = blockIdx.x & 7;
    const int row0 = bm*32;
    const int ncol0 = bn*32;           // 0..127 -> ti ; 128..255 -> tj
    {
        const float4* src = (const float4*)(g_h + (size_t)row0*DD);
        float4* dst = (float4*)sA;
        #pragma unroll
        for (int idx = t; idx < 32*DD/4; idx += 256) dst[idx] = src[idx];
    }
    {
        const int koff = (ncol0 >= DD) ? DD : 0;
        const int c0g  = ncol0 & (DD-1);
        #pragma unroll
        for (int idx = t; idx < DD*8; idx += 256) {
            int k = idx >> 3, cc = (idx & 7)*4;
            *(float4*)&sW[k*32 + cc] =
                *(const float4*)&We1[(size_t)(koff + k)*DD + c0g + cc];
        }
    }
    __syncthreads();
    const int r0 = (t >> 5)*4, c0 = t & 31;
    float a0=0,a1=0,a2=0,a3=0;
    #pragma unroll 4
    for (int k = 0; k < DD; k++){
        float wv = sW[k*32 + c0];
        a0 += sA[(r0+0)*DD + k]*wv;
        a1 += sA[(r0+1)*DD + k]*wv;
        a2 += sA[(r0+2)*DD + k]*wv;
        a3 += sA[(r0+3)*DD + k]*wv;
    }
    if (ncol0 < DD) {
        const float b0 = be1[ncol0 + c0];
        float* o = g_ti + (size_t)(row0 + r0)*DD + ncol0 + c0;
        o[0] = a0+b0; o[DD] = a1+b0; o[2*DD] = a2+b0; o[3*DD] = a3+b0;
    } else {
        float* o = g_tj + (size_t)(row0 + r0)*DD + (ncol0 - DD) + c0;
        o[0] = a0; o[DD] = a1; o[2*DD] = a2; o[3*DD] = a3;
    }
}

// u = lrelu([h, mpre] @ Wh1 + bh1).  K=256 in 2 chunks.  Grid = 64*4 = 256.
__global__ void __launch_bounds__(256)
k_u1_g(const float* __restrict__ Wh1, const float* __restrict__ bh1){
    __shared__ float sA[32*DD];
    __shared__ float sW[DD*32];
    const int t = threadIdx.x;
    const int bm = blockIdx.x >> 2, bn = blockIdx.x & 3;
    const int row0 = bm*32, ncol0 = bn*32;
    const int r0 = (t >> 5)*4, c0 = t & 31;
    float a0=0,a1=0,a2=0,a3=0;
    #pragma unroll
    for (int ch = 0; ch < 2; ch++){
        {
            const float* base = (ch == 0) ? g_h : g_mpre;
            const float4* src = (const float4*)(base + (size_t)row0*DD);
            float4* dst = (float4*)sA;
            #pragma unroll
            for (int idx = t; idx < 32*DD/4; idx += 256) dst[idx] = src[idx];
        }
        #pragma unroll
        for (int idx = t; idx < DD*8; idx += 256) {
            int k = idx >> 3, cc = (idx & 7)*4;
            *(float4*)&sW[k*32 + cc] =
                *(const float4*)&Wh1[(size_t)(ch*DD + k)*DD + ncol0 + cc];
        }
        __syncthreads();
        #pragma unroll 4
        for (int k = 0; k < DD; k++){
            float wv = sW[k*32 + c0];
            a0 += sA[(r0+0)*DD + k]*wv;
            a1 += sA[(r0+1)*DD + k]*wv;
            a2 += sA[(r0+2)*DD + k]*wv;
            a3 += sA[(r0+3)*DD + k]*wv;
        }
        __syncthreads();
    }
    const float b0 = bh1[ncol0 + c0];
    float* o = g_u + (size_t)(row0 + r0)*DD + ncol0 + c0;
    o[0]    = lrelu(a0+b0);
    o[DD]   = lrelu(a1+b0);
    o[2*DD] = lrelu(a2+b0);
    o[3*DD] = lrelu(a3+b0);
}

// hnew = u @ Wh2 + bh2 + h.  Writes g_h (out==null) or out.  Grid = 256.
__global__ void __launch_bounds__(256)
k_u2_g(const float* __restrict__ Wh2, const float* __restrict__ bh2,
       float* __restrict__ out){
    __shared__ float sA[32*DD];
    __shared__ float sW[DD*32];
    const int t = threadIdx.x;
    const int bm = blockIdx.x >> 2, bn = blockIdx.x & 3;
    const int row0 = bm*32, ncol0 = bn*32;
    {
        const float4* src = (const float4*)(g_u + (size_t)row0*DD);
        float4* dst = (float4*)sA;
        #pragma unroll
        for (int idx = t; idx < 32*DD/4; idx += 256) dst[idx] = src[idx];
    }
    #pragma unroll
    for (int idx = t; idx < DD*8; idx += 256) {
        int k = idx >> 3, cc = (idx & 7)*4;
        *(float4*)&sW[k*32 + cc] = *(const float4*)&Wh2[(size_t)k*DD + ncol0 + cc];
    }
    __syncthreads();
    const int r0 = (t >> 5)*4, c0 = t & 31;
    float a0=0,a1=0,a2=0,a3=0;
    #pragma unroll 4
    for (int k = 0; k < DD; k++){
        float wv = sW[k*32 + c0];
        a0 += sA[(r0+0)*DD + k]*wv;
        a1 += sA[(r0+1)*DD + k]*wv;
        a2 += sA[(r0+2)*DD + k]*wv;
        a3 += sA[(r0+3)*DD + k]*wv;
    }
    const float b0 = bh2[ncol0 + c0];
    float* hb = g_h + (size_t)(row0 + r0)*DD + ncol0 + c0;
    float* o  = out ? (out + (size_t)(row0 + r0)*DD + ncol0 + c0) : hb;
    o[0]    = a0+b0+hb[0];
    o[DD]   = a1+b0+hb[DD];
    o[2*DD] = a2+b0+hb[2*DD];
    o[3*DD] = a3+b0+hb[3*DD];
}

// ---------------------------------------------------------------------------
// K4: edge kernel — fp16 m16n8k16 mma.sync (fp32 accum).
// Persistent grid=148, 8 warps = 4(j) x 2(c), warp tile 64x64.
// ---------------------------------------------------------------------------
__global__ void __launch_bounds__(256, 1)
k_edge(const float* __restrict__ be2,
       const float* __restrict__ Winf,
       const float* __restrict__ binf,
       const float* __restrict__ We1,
       const float* __restrict__ We2,
       const float* __restrict__ coords,
       int ntiles)
{
    extern __shared__ char smraw[];
    __half* sWt = (__half*)smraw;                   // 128*SWH*2 = 34816 B  [c][k]
    __half* sXh = (__half*)(smraw + 34816);         // 256*SXH*2 = 69632 B  [j][k]
    float* sC  = (float*)(smraw + 104448);          // 3*256
    float* sEp = sC  + 3*RR;                        // 256
    float* sE  = sEp + RR;                          // 256
    float* sTi = sE  + RR;                          // 128
    float* sWd = sTi + DD;                          // 128
    float* sMp = sWd + DD;                          // 128
    float* sBc = sMp + DD;                          // 128
    float* sWc = sBc + DD;                          // 128

    const int t    = threadIdx.x;
    const int w    = t >> 5;
    const int lane = t & 31;
    const int g    = lane >> 2;
    const int tig  = lane & 3;
    const int jbase = (w >> 1) * 64;
    const int cbase = (w & 1) * 64;

    // one-time: W_e2 transposed into [c][k] halves
    for (int idx = t; idx < DD*DD; idx += 256) {
        int k = idx >> 7, c = idx & 127;
        sWt[c*SWH + k] = __float2half_rn(We2[idx]);
    }
    if (t < DD) {
        sWd[t] = We1[2*DD*DD + t];
        sBc[t] = be2[t];
        sWc[t] = Winf[t];
    }
    const float bi = binf[0];
    __syncthreads();

    for (int tile = blockIdx.x; tile < ntiles; tile += gridDim.x) {
        const int b = tile >> 8, i = tile & 255;

        {
            const float* cp = coords + ((size_t)b*RR + t)*3;
            sC[t] = cp[0]; sC[RR + t] = cp[1]; sC[2*RR + t] = cp[2];
        }
        if (t < DD) { sTi[t] = g_ti[(size_t)tile*DD + t]; sMp[t] = 0.f; }
        sEp[t] = 0.f;
        __syncthreads();

        // ---- build X (warp per j row, lane per k-quad) as fp16 ----
        {
            const float* tjb = g_tj + (size_t)b*RR*DD;
            const int k4 = lane*4;
            const float ti0 = sTi[k4], ti1 = sTi[k4+1], ti2 = sTi[k4+2], ti3 = sTi[k4+3];
            const float wd0 = sWd[k4], wd1 = sWd[k4+1], wd2 = sWd[k4+2], wd3 = sWd[k4+3];
            const float cix = sC[i], ciy = sC[RR + i], ciz = sC[2*RR + i];
            #pragma unroll
            for (int j = w; j < RR; j += 16) {
                const int j1 = j + 8;
                float4 tv0 = *(const float4*)&tjb[(size_t)j *DD + k4];
                float4 tv1 = *(const float4*)&tjb[(size_t)j1*DD + k4];
                float dx0 = sC[j ] - cix, dy0 = sC[RR+j ] - ciy, dz0 = sC[2*RR+j ] - ciz;
                float dx1 = sC[j1] - cix, dy1 = sC[RR+j1] - ciy, dz1 = sC[2*RR+j1] - ciz;
                float d20 = dx0*dx0 + dy0*dy0 + dz0*dz0;
                float d21 = dx1*dx1 + dy1*dy1 + dz1*dz1;
                __half2 h01 = __floats2half2_rn(lrelu(ti0 + tv0.x + d20*wd0),
                                                lrelu(ti1 + tv0.y + d20*wd1));
                __half2 h23 = __floats2half2_rn(lrelu(ti2 + tv0.z + d20*wd2),
                                                lrelu(ti3 + tv0.w + d20*wd3));
                uint2 u0; u0.x = *(uint32_t*)&h01; u0.y = *(uint32_t*)&h23;
                *(uint2*)&sXh[(size_t)j*SXH + k4] = u0;
                __half2 h45 = __floats2half2_rn(lrelu(ti0 + tv1.x + d21*wd0),
                                                lrelu(ti1 + tv1.y + d21*wd1));
                __half2 h67 = __floats2half2_rn(lrelu(ti2 + tv1.z + d21*wd2),
                                                lrelu(ti3 + tv1.w + d21*wd3));
                uint2 u1; u1.x = *(uint32_t*)&h45; u1.y = *(uint32_t*)&h67;
                *(uint2*)&sXh[(size_t)j1*SXH + k4] = u1;
            }
        }
        __syncthreads();

        // ---- mainloop: 64x64 warp tile, m16n8k16 fp16 ----
        float acc[4][8][4];
        #pragma unroll
        for (int mi = 0; mi < 4; mi++)
            #pragma unroll
            for (int ni = 0; ni < 8; ni++)
                #pragma unroll
                for (int q = 0; q < 4; q++) acc[mi][ni][q] = 0.f;

        #pragma unroll 4
        for (int k0 = 0; k0 < DD; k0 += 16) {
            uint32_t A[4][4];
            #pragma unroll
            for (int mi = 0; mi < 4; mi++) {
                const __half* xr = sXh + (jbase + mi*16 + g)*SXH + k0 + tig*2;
                A[mi][0] = *(const uint32_t*)(xr);
                A[mi][1] = *(const uint32_t*)(xr + 8*SXH);
                A[mi][2] = *(const uint32_t*)(xr + 8);
                A[mi][3] = *(const uint32_t*)(xr + 8*SXH + 8);
            }
            uint32_t Bf[8][2];
            #pragma unroll
            for (int ni = 0; ni < 8; ni++) {
                const __half* wr = sWt + (cbase + ni*8 + g)*SWH + k0 + tig*2;
                Bf[ni][0] = *(const uint32_t*)(wr);
                Bf[ni][1] = *(const uint32_t*)(wr + 8);
            }
            #pragma unroll
            for (int mi = 0; mi < 4; mi++)
                #pragma unroll
                for (int ni = 0; ni < 8; ni++)
                    asm volatile(
                        "mma.sync.aligned.m16n8k16.row.col.f32.f16.f16.f32 "
                        "{%0,%1,%2,%3}, {%4,%5,%6,%7}, {%8,%9}, {%0,%1,%2,%3};"
                        : "+f"(acc[mi][ni][0]), "+f"(acc[mi][ni][1]),
                          "+f"(acc[mi][ni][2]), "+f"(acc[mi][ni][3])
                        : "r"(A[mi][0]), "r"(A[mi][1]), "r"(A[mi][2]), "r"(A[mi][3]),
                          "r"(Bf[ni][0]), "r"(Bf[ni][1]));
        }

        // ---- epilogue ----
        float bc[16], wc[16];
        #pragma unroll
        for (int ni = 0; ni < 8; ni++)
            #pragma unroll
            for (int q = 0; q < 2; q++) {
                int c = cbase + ni*8 + tig*2 + q;
                bc[ni*2+q] = sBc[c];
                wc[ni*2+q] = sWc[c];
            }

        // pass 1: per-j gate logit partials
        #pragma unroll
        for (int mi = 0; mi < 4; mi++)
            #pragma unroll
            for (int r = 0; r < 2; r++) {
                float p = 0.f;
                #pragma unroll
                for (int ni = 0; ni < 8; ni++)
                    #pragma unroll
                    for (int q = 0; q < 2; q++)
                        p += lrelu(acc[mi][ni][r*2+q] + bc[ni*2+q]) * wc[ni*2+q];
                p += __shfl_xor_sync(0xffffffffu, p, 1);
                p += __shfl_xor_sync(0xffffffffu, p, 2);
                if (tig == 0) atomicAdd(&sEp[jbase + mi*16 + g + r*8], p);
            }
        __syncthreads();
        {
            float s = sEp[t] + bi;
            sE[t] = (t == i) ? 0.f : __fdividef(1.f, 1.f + __expf(-s));
        }
        __syncthreads();

        // pass 2: mpre[c] = sum_j m*e
        float macc[16];
        #pragma unroll
        for (int q = 0; q < 16; q++) macc[q] = 0.f;
        #pragma unroll
        for (int mi = 0; mi < 4; mi++)
            #pragma unroll
            for (int r = 0; r < 2; r++) {
                float e = sE[jbase + mi*16 + g + r*8];
                #pragma unroll
                for (int ni = 0; ni < 8; ni++)
                    #pragma unroll
                    for (int q = 0; q < 2; q++)
                        macc[ni*2+q] += lrelu(acc[mi][ni][r*2+q] + bc[ni*2+q]) * e;
            }
        #pragma unroll
        for (int q = 0; q < 16; q++) {
            macc[q] += __shfl_xor_sync(0xffffffffu, macc[q], 4);
            macc[q] += __shfl_xor_sync(0xffffffffu, macc[q], 8);
            macc[q] += __shfl_xor_sync(0xffffffffu, macc[q], 16);
        }
        if (g == 0) {
            #pragma unroll
            for (int q = 0; q < 16; q++)
                atomicAdd(&sMp[cbase + (q >> 1)*8 + tig*2 + (q & 1)], macc[q]);
        }
        __syncthreads();
        if (t < DD) g_mpre[(size_t)tile*DD + t] = sMp[t];
        __syncthreads();
    }
}

// ---------------------------------------------------------------------------
extern "C" void kernel_launch(void* const* d_in, const int* in_sizes, int n_in,
                              void* d_out, int out_size)
{
    const float* fres   = (const float*)d_in[0];
    const float* coords = (const float*)d_in[1];
    const float* Wemb   = (const float*)d_in[2];
    const float* We1    = (const float*)d_in[3];
    const float* be1    = (const float*)d_in[4];
    const float* We2    = (const float*)d_in[5];
    const float* be2    = (const float*)d_in[6];
    const float* Winf   = (const float*)d_in[7];
    const float* binf   = (const float*)d_in[8];
    const float* Wh1    = (const float*)d_in[9];
    const float* bh1    = (const float*)d_in[10];
    const float* Wh2    = (const float*)d_in[11];
    const float* bh2    = (const float*)d_in[12];
    float* out = (float*)d_out;

    const int EDGE_SMEM = 104448 + (3*RR + RR + RR + 5*DD)*(int)sizeof(float);  // 112128
    cudaFuncSetAttribute(k_edge, cudaFuncAttributeMaxDynamicSharedMemorySize, EDGE_SMEM);

    k_embed<<<NROW, DD>>>(fres, Wemb);
    k_titj_g<<<(NROW/32)*8, 256>>>(We1, be1);
    k_edge<<<148, 256, EDGE_SMEM>>>(be2, Winf, binf, We1, We2, coords, NROW);
    k_u1_g<<<(NROW/32)*4, 256>>>(Wh1, bh1);
    k_u2_g<<<(NROW/32)*4, 256>>>(Wh2, bh2, nullptr);
    k_titj_g<<<(NROW/32)*8, 256>>>(We1, be1);
    k_edge<<<148, 256, EDGE_SMEM>>>(be2, Winf, binf, We1, We2, coords, NROW);
    k_u1_g<<<(NROW/32)*4, 256>>>(Wh1, bh1);
    k_u2_g<<<(NROW/32)*4, 256>>>(Wh2, bh2, out);
}